// round 5
// baseline (speedup 1.0000x reference)
#include <cuda_runtime.h>
#include <stdint.h>

// Problem constants (fixed by the dataset)
#define NN 50000
#define EE 800000
#define HH 3
#define OO 64
#define FT 192   // HH*OO

// ---------------- scratch (device globals; allocation-free) ----------------
__device__ __align__(16) float g_fs[(size_t)NN * FT];
__device__ __align__(16) float g_fd[(size_t)NN * FT];
__device__ __align__(16) float g_ha[(size_t)NN * FT];
__device__ __align__(16) float g_hb[(size_t)NN * FT];
__device__ __align__(16) float g_elog[(size_t)EE * HH];
__device__ int g_deg[NN];
__device__ int g_off[NN + 1];
__device__ int g_cur[NN];
__device__ int g_ss[EE];         // src ids sorted by dst
__device__ int g_sd[EE];         // dst ids sorted by dst
__device__ __align__(16) float g_pool[128 * OO];
__device__ __align__(16) float g_cnt[128];

__device__ __forceinline__ float lrelu(float x, float s) { return x > 0.f ? x : s * x; }

__device__ __forceinline__ uint32_t rna(uint32_t rawf32) {
    uint32_t u;
    asm("cvt.rna.tf32.f32 %0, %1;" : "=r"(u) : "r"(rawf32));
    return u;
}

// ---------------- CSR construction (counting sort by dst) ----------------
__global__ void hist_kernel(const int* __restrict__ dst, int* __restrict__ deg, int E) {
    int e = blockIdx.x * blockDim.x + threadIdx.x;
    if (e < E) atomicAdd(&deg[dst[e]], 1);
}

__global__ void scan_kernel(const int* __restrict__ deg, int* __restrict__ off,
                            int* __restrict__ cur, int N, int E) {
    __shared__ int ssum[1024];
    int t = threadIdx.x;
    const int CH = (N + 1023) / 1024;
    int a = t * CH;
    int b = a + CH < N ? a + CH : N;
    int s = 0;
    for (int i = a; i < b; i++) s += deg[i];
    ssum[t] = s;
    __syncthreads();
    #pragma unroll
    for (int o = 1; o < 1024; o <<= 1) {
        int v = (t >= o) ? ssum[t - o] : 0;
        __syncthreads();
        ssum[t] += v;
        __syncthreads();
    }
    int base = (t == 0) ? 0 : ssum[t - 1];
    for (int i = a; i < b; i++) {
        off[i] = base; cur[i] = base; base += deg[i];
    }
    if (t == 1023) off[N] = E;
}

__global__ void scatter_kernel(const int* __restrict__ src, const int* __restrict__ dst,
                               int* __restrict__ cur, int* __restrict__ ss,
                               int* __restrict__ sd, int E) {
    int e = blockIdx.x * blockDim.x + threadIdx.x;
    if (e >= E) return;
    int d = dst[e];
    int p = atomicAdd(&cur[d], 1);
    ss[p] = src[e];
    sd[p] = d;
}

// ---------------- TF32 GEMM with cp.async double buffering ----------------
// C[M,Nc] = A[M,K] @ W[K,Nc] + bias. Tile 128x64x32, 8 warps (4x2), warp 32x32.
// fp32 staged raw to SMEM via cp.async; cvt.rna.tf32 applied per-fragment in
// registers before MMA (restores R2/R3 numerics).
#define GBM 128
#define GBN 64
#define GBK 32
#define AROW 36    // 36 % 32 == 4 -> fragment bank 4*gid+tig unique
#define BROW 72    // 72 % 32 == 8 -> fragment bank 8*tig+gid unique

__device__ __forceinline__ void cpa16(uint32_t dst, const void* src) {
    asm volatile("cp.async.cg.shared.global [%0], [%1], 16;" :: "r"(dst), "l"(src));
}

__global__ __launch_bounds__(256) void gemm_tf32(
    const float* __restrict__ A, const float* __restrict__ W,
    const float* __restrict__ bias, float* __restrict__ C,
    int M, int K, int Nc)
{
    extern __shared__ uint32_t sh[];
    uint32_t* As = sh;                          // [2][GBM][AROW]
    uint32_t* Bs = sh + 2 * GBM * AROW;         // [2][GBK][BROW]

    const int tid  = threadIdx.x;
    const int wid  = tid >> 5;
    const int lane = tid & 31;
    const int warpM = wid >> 1;
    const int warpN = wid & 1;
    const int gid = lane >> 2;
    const int tig = lane & 3;
    const int row0 = blockIdx.y * GBM;
    const int col0 = blockIdx.x * GBN;

    const int nch = K / GBK;
    float c[2][4][4] = {};

    #define STAGE(ch, buf) do {                                                   \
        int k0_ = (ch) * GBK;                                                     \
        _Pragma("unroll")                                                         \
        for (int i = 0; i < 4; i++) {                                             \
            int cc = tid + 256 * i;                    /* 0..1023 */              \
            int r  = cc >> 3;                          /* 0..127 */               \
            int kc = (cc & 7) << 2;                    /* 0,4..28 */              \
            uint32_t* dp = As + ((buf) * GBM + r) * AROW + kc;                    \
            if (row0 + r < M)                                                     \
                cpa16((uint32_t)__cvta_generic_to_shared(dp),                     \
                      A + (size_t)(row0 + r) * K + k0_ + kc);                     \
            else                                                                  \
                *(uint4*)dp = make_uint4(0u, 0u, 0u, 0u);                         \
        }                                                                         \
        _Pragma("unroll")                                                         \
        for (int i = 0; i < 2; i++) {                                             \
            int cc = tid + 256 * i;                    /* 0..511 */               \
            int r  = cc >> 4;                          /* 0..31 */                \
            int nc = (cc & 15) << 2;                   /* 0..60 */                \
            uint32_t* dp = Bs + ((buf) * GBK + r) * BROW + nc;                    \
            cpa16((uint32_t)__cvta_generic_to_shared(dp),                         \
                  W + (size_t)(k0_ + r) * Nc + col0 + nc);                        \
        }                                                                         \
        asm volatile("cp.async.commit_group;");                                   \
    } while (0)

    STAGE(0, 0);

    for (int ch = 0; ch < nch; ch++) {
        int buf = ch & 1;
        if (ch + 1 < nch) {
            STAGE(ch + 1, buf ^ 1);
            asm volatile("cp.async.wait_group 1;");
        } else {
            asm volatile("cp.async.wait_group 0;");
        }
        __syncthreads();

        const uint32_t* Ab = As + buf * GBM * AROW;
        const uint32_t* Bb = Bs + buf * GBK * BROW;

        #pragma unroll
        for (int ks = 0; ks < 4; ks++) {
            const int kk = ks * 8;
            uint32_t a[2][4], b[4][2];
            #pragma unroll
            for (int mi = 0; mi < 2; mi++) {
                int rb = warpM * 32 + mi * 16;
                a[mi][0] = rna(Ab[(rb + gid) * AROW + kk + tig]);
                a[mi][1] = rna(Ab[(rb + gid + 8) * AROW + kk + tig]);
                a[mi][2] = rna(Ab[(rb + gid) * AROW + kk + tig + 4]);
                a[mi][3] = rna(Ab[(rb + gid + 8) * AROW + kk + tig + 4]);
            }
            #pragma unroll
            for (int ni = 0; ni < 4; ni++) {
                int cb = warpN * 32 + ni * 8;
                b[ni][0] = rna(Bb[(kk + tig) * BROW + cb + gid]);
                b[ni][1] = rna(Bb[(kk + tig + 4) * BROW + cb + gid]);
            }
            #pragma unroll
            for (int mi = 0; mi < 2; mi++)
                #pragma unroll
                for (int ni = 0; ni < 4; ni++)
                    asm volatile(
                        "mma.sync.aligned.m16n8k8.row.col.f32.tf32.tf32.f32 "
                        "{%0,%1,%2,%3}, {%4,%5,%6,%7}, {%8,%9}, {%0,%1,%2,%3};"
                        : "+f"(c[mi][ni][0]), "+f"(c[mi][ni][1]),
                          "+f"(c[mi][ni][2]), "+f"(c[mi][ni][3])
                        : "r"(a[mi][0]), "r"(a[mi][1]), "r"(a[mi][2]), "r"(a[mi][3]),
                          "r"(b[ni][0]), "r"(b[ni][1]));
        }
        __syncthreads();
    }
    #undef STAGE

    #pragma unroll
    for (int mi = 0; mi < 2; mi++) {
        #pragma unroll
        for (int ni = 0; ni < 4; ni++) {
            int gcol = col0 + warpN * 32 + ni * 8 + tig * 2;
            float bx = bias[gcol], by = bias[gcol + 1];
            int r0 = row0 + warpM * 32 + mi * 16 + gid;
            if (r0 < M) {
                float2 o = make_float2(c[mi][ni][0] + bx, c[mi][ni][1] + by);
                *(float2*)(C + (size_t)r0 * Nc + gcol) = o;
            }
            int r1 = r0 + 8;
            if (r1 < M) {
                float2 o = make_float2(c[mi][ni][2] + bx, c[mi][ni][3] + by);
                *(float2*)(C + (size_t)r1 * Nc + gcol) = o;
            }
        }
    }
}

// ---------------- edge logits: one warp per dst-sorted edge ----------------
// dst-sorted order -> fd[dst] rows are L1-resident across consecutive edges.
__global__ __launch_bounds__(256) void edge_logits_sorted(
    const float* __restrict__ fs, const float* __restrict__ fd,
    const int* __restrict__ ss, const int* __restrict__ sd,
    const float* __restrict__ attn, float* __restrict__ elog, int E)
{
    __shared__ float sattn[FT];
    if (threadIdx.x < FT) sattn[threadIdx.x] = attn[threadIdx.x];
    __syncthreads();
    int e = blockIdx.x * 8 + (threadIdx.x >> 5);
    int lane = threadIdx.x & 31;
    if (e >= E) return;
    int s = ss[e], d = sd[e];
    const float4* ps = (const float4*)(fs + (size_t)s * FT);
    const float4* pd = (const float4*)(fd + (size_t)d * FT);
    const float4* pa = (const float4*)sattn;

    float acc0 = 0.f, acc1 = 0.f, acc2 = 0.f;
    {
        float4 a = ps[lane], b = pd[lane], t = pa[lane];
        float v = lrelu(a.x + b.x, 0.2f) * t.x + lrelu(a.y + b.y, 0.2f) * t.y
                + lrelu(a.z + b.z, 0.2f) * t.z + lrelu(a.w + b.w, 0.2f) * t.w;
        if (lane < 16) acc0 = v; else acc1 = v;
    }
    if (lane < 16) {
        float4 a = ps[32 + lane], b = pd[32 + lane], t = pa[32 + lane];
        acc2 = lrelu(a.x + b.x, 0.2f) * t.x + lrelu(a.y + b.y, 0.2f) * t.y
             + lrelu(a.z + b.z, 0.2f) * t.z + lrelu(a.w + b.w, 0.2f) * t.w;
    }
    #pragma unroll
    for (int o = 16; o; o >>= 1) {
        acc0 += __shfl_xor_sync(0xffffffffu, acc0, o);
        acc1 += __shfl_xor_sync(0xffffffffu, acc1, o);
        acc2 += __shfl_xor_sync(0xffffffffu, acc2, o);
    }
    if (lane < 3) elog[(size_t)e * 3 + lane] = (lane == 0 ? acc0 : (lane == 1 ? acc1 : acc2));
}

// ---------------- node aggregate: warp per node; max, then exp+den+acc fused --
__global__ __launch_bounds__(256) void node_agg_kernel(
    const float* __restrict__ fs, const int* __restrict__ off,
    const int* __restrict__ ss, const float* __restrict__ elog,
    float* __restrict__ hout, int N)
{
    int node = blockIdx.x * 8 + (threadIdx.x >> 5);
    int lane = threadIdx.x & 31;
    if (node >= N) return;
    int e0 = off[node], e1 = off[node + 1];

    // lane-parallel max over edges
    float mx0 = -3.0e38f, mx1 = -3.0e38f, mx2 = -3.0e38f;
    for (int p = e0 + lane; p < e1; p += 32) {
        mx0 = fmaxf(mx0, elog[(size_t)p * 3 + 0]);
        mx1 = fmaxf(mx1, elog[(size_t)p * 3 + 1]);
        mx2 = fmaxf(mx2, elog[(size_t)p * 3 + 2]);
    }
    #pragma unroll
    for (int o = 16; o; o >>= 1) {
        mx0 = fmaxf(mx0, __shfl_xor_sync(0xffffffffu, mx0, o));
        mx1 = fmaxf(mx1, __shfl_xor_sync(0xffffffffu, mx1, o));
        mx2 = fmaxf(mx2, __shfl_xor_sync(0xffffffffu, mx2, o));
    }

    // fused exp + den + unnormalized aggregation
    float acc[6] = {};
    float den0 = 0.f, den1 = 0.f, den2 = 0.f;
    #pragma unroll 2
    for (int p = e0; p < e1; p++) {
        float w0 = __expf(elog[(size_t)p * 3 + 0] - mx0);
        float w1 = __expf(elog[(size_t)p * 3 + 1] - mx1);
        float w2 = __expf(elog[(size_t)p * 3 + 2] - mx2);
        den0 += w0; den1 += w1; den2 += w2;
        const float* fp = fs + (size_t)ss[p] * FT;
        acc[0] = fmaf(w0, fp[lane],       acc[0]);
        acc[1] = fmaf(w0, fp[32 + lane],  acc[1]);
        acc[2] = fmaf(w1, fp[64 + lane],  acc[2]);
        acc[3] = fmaf(w1, fp[96 + lane],  acc[3]);
        acc[4] = fmaf(w2, fp[128 + lane], acc[4]);
        acc[5] = fmaf(w2, fp[160 + lane], acc[5]);
    }
    float r0 = 1.f / fmaxf(den0, 1e-9f);
    float r1 = 1.f / fmaxf(den1, 1e-9f);
    float r2 = 1.f / fmaxf(den2, 1e-9f);
    float* po = hout + (size_t)node * FT;
    po[lane]       = acc[0] * r0;
    po[32 + lane]  = acc[1] * r0;
    po[64 + lane]  = acc[2] * r1;
    po[96 + lane]  = acc[3] * r1;
    po[128 + lane] = acc[4] * r2;
    po[160 + lane] = acc[5] * r2;
}

// ---------------- head-mean + per-graph pooling ----------------
__global__ void pool_kernel(const float* __restrict__ h, const int* __restrict__ gid,
                            float* __restrict__ pool, float* __restrict__ cnt, int N) {
    int idx = blockIdx.x * blockDim.x + threadIdx.x;
    if (idx >= N * OO) return;
    int n = idx >> 6, k = idx & 63;
    const float* p = h + (size_t)n * FT;
    float v = (p[k] + p[64 + k] + p[128 + k]) * (1.0f / 3.0f);
    int g = gid[n];
    atomicAdd(&pool[g * OO + k], v);
    if (k == 0) atomicAdd(&cnt[g], 1.0f);
}

// ---------------- final MLP: 64 -> 64 -> 32 -> 2, leaky 0.01 ----------------
__global__ void mlp_kernel(const float* __restrict__ pool, const float* __restrict__ cnt,
                           const float* __restrict__ W1, const float* __restrict__ b1,
                           const float* __restrict__ W2, const float* __restrict__ b2,
                           const float* __restrict__ W3, const float* __restrict__ b3,
                           float* __restrict__ out) {
    int g = blockIdx.x;
    int j = threadIdx.x;  // 64 threads
    __shared__ float gv[64], t1[64], t2[32];
    float c = fmaxf(cnt[g], 1.0f);
    gv[j] = pool[g * OO + j] / c;
    __syncthreads();
    float a = b1[j];
    #pragma unroll 8
    for (int k = 0; k < 64; k++) a = fmaf(gv[k], W1[k * 64 + j], a);
    t1[j] = lrelu(a, 0.01f);
    __syncthreads();
    if (j < 32) {
        float a2 = b2[j];
        #pragma unroll 8
        for (int k = 0; k < 64; k++) a2 = fmaf(t1[k], W2[k * 32 + j], a2);
        t2[j] = lrelu(a2, 0.01f);
    }
    __syncthreads();
    if (j < 2) {
        float a3 = b3[j];
        #pragma unroll
        for (int k = 0; k < 32; k++) a3 = fmaf(t2[k], W3[k * 2 + j], a3);
        out[g * 2 + j] = lrelu(a3, 0.01f);
    }
}

// ---------------- launcher ----------------
extern "C" void kernel_launch(void* const* d_in, const int* in_sizes, int n_in,
                              void* d_out, int out_size) {
    const float* x   = (const float*)d_in[0];
    const int*   src = (const int*)d_in[1];
    const int*   dst = (const int*)d_in[2];
    const int*   gid = (const int*)d_in[3];
    const float* Wsrc[3] = {(const float*)d_in[5],  (const float*)d_in[10], (const float*)d_in[15]};
    const float* bsrc[3] = {(const float*)d_in[6],  (const float*)d_in[11], (const float*)d_in[16]};
    const float* Wdst[3] = {(const float*)d_in[7],  (const float*)d_in[12], (const float*)d_in[17]};
    const float* bdst[3] = {(const float*)d_in[8],  (const float*)d_in[13], (const float*)d_in[18]};
    const float* attn[3] = {(const float*)d_in[9],  (const float*)d_in[14], (const float*)d_in[19]};
    const float* W1 = (const float*)d_in[20];
    const float* b1 = (const float*)d_in[21];
    const float* W2 = (const float*)d_in[22];
    const float* b2 = (const float*)d_in[23];
    const float* W3 = (const float*)d_in[24];
    const float* b3 = (const float*)d_in[25];

    const int N  = in_sizes[0] / 128;
    const int E  = in_sizes[1];
    const int ng = out_size / 2;

    float *fs, *fd, *ha, *hb, *elog, *pool, *cnt;
    int *deg, *off, *cur, *ssorted, *dsorted;
    cudaGetSymbolAddress((void**)&fs,   g_fs);
    cudaGetSymbolAddress((void**)&fd,   g_fd);
    cudaGetSymbolAddress((void**)&ha,   g_ha);
    cudaGetSymbolAddress((void**)&hb,   g_hb);
    cudaGetSymbolAddress((void**)&elog, g_elog);
    cudaGetSymbolAddress((void**)&deg,  g_deg);
    cudaGetSymbolAddress((void**)&off,  g_off);
    cudaGetSymbolAddress((void**)&cur,  g_cur);
    cudaGetSymbolAddress((void**)&ssorted, g_ss);
    cudaGetSymbolAddress((void**)&dsorted, g_sd);
    cudaGetSymbolAddress((void**)&pool, g_pool);
    cudaGetSymbolAddress((void**)&cnt,  g_cnt);

    // GEMM dynamic smem (55296 B > 48 KB static limit)
    const int GEMM_SMEM = (2 * GBM * AROW + 2 * GBK * BROW) * 4;
    cudaFuncSetAttribute(gemm_tf32, cudaFuncAttributeMaxDynamicSharedMemorySize, GEMM_SMEM);

    // ---- CSR build (once; reused by all 3 layers)
    cudaMemsetAsync(deg, 0, (size_t)N * sizeof(int), 0);
    hist_kernel<<<(E + 255) / 256, 256>>>(dst, deg, E);
    scan_kernel<<<1, 1024>>>(deg, off, cur, N, E);
    scatter_kernel<<<(E + 255) / 256, 256>>>(src, dst, cur, ssorted, dsorted, E);

    const float* hin = x;
    int Fin = 128;
    float* houts[3] = {ha, hb, ha};
    const int edgeBlocks = (E + 7) / 8;
    const int nodeBlocks = (N + 7) / 8;

    for (int l = 0; l < 3; l++) {
        dim3 gg(FT / GBN, (N + GBM - 1) / GBM);
        gemm_tf32<<<gg, 256, GEMM_SMEM>>>(hin, Wsrc[l], bsrc[l], fs, N, Fin, FT);
        gemm_tf32<<<gg, 256, GEMM_SMEM>>>(hin, Wdst[l], bdst[l], fd, N, Fin, FT);
        edge_logits_sorted<<<edgeBlocks, 256>>>(fs, fd, ssorted, dsorted, attn[l], elog, E);
        node_agg_kernel<<<nodeBlocks, 256>>>(fs, off, ssorted, elog, houts[l], N);
        hin = houts[l];
        Fin = FT;
    }

    cudaMemsetAsync(pool, 0, 128 * OO * sizeof(float), 0);
    cudaMemsetAsync(cnt,  0, 128 * sizeof(float), 0);
    pool_kernel<<<(N * OO + 255) / 256, 256>>>(hin, gid, pool, cnt, N);
    mlp_kernel<<<ng, 64>>>(pool, cnt, W1, b1, W2, b2, W3, b3, (float*)d_out);
}

// round 6
// speedup vs baseline: 1.3177x; 1.3177x over previous
#include <cuda_runtime.h>
#include <stdint.h>

// Problem constants (fixed by the dataset)
#define NN 50000
#define EE 800000
#define HH 3
#define OO 64
#define FT 192   // HH*OO

// ---------------- scratch (device globals; allocation-free) ----------------
__device__ __align__(16) float g_fs[(size_t)NN * FT];
__device__ __align__(16) float g_fd[(size_t)NN * FT];
__device__ __align__(16) float g_ha[(size_t)NN * FT];
__device__ __align__(16) float g_hb[(size_t)NN * FT];
__device__ int g_deg[NN];
__device__ int g_off[NN + 1];
__device__ int g_cur[NN];
__device__ int g_ss[EE];         // src ids sorted by dst
__device__ __align__(16) float g_pool[128 * OO];
__device__ __align__(16) float g_cnt[128];

__device__ __forceinline__ float lrelu(float x, float s) { return x > 0.f ? x : s * x; }

__device__ __forceinline__ uint32_t rna(uint32_t rawf32) {
    uint32_t u;
    asm("cvt.rna.tf32.f32 %0, %1;" : "=r"(u) : "r"(rawf32));
    return u;
}

// ---------------- CSR construction (counting sort by dst) ----------------
__global__ void hist_kernel(const int* __restrict__ dst, int* __restrict__ deg, int E) {
    int e = blockIdx.x * blockDim.x + threadIdx.x;
    if (e < E) atomicAdd(&deg[dst[e]], 1);
}

__global__ void scan_kernel(const int* __restrict__ deg, int* __restrict__ off,
                            int* __restrict__ cur, int N, int E) {
    __shared__ int ssum[1024];
    int t = threadIdx.x;
    const int CH = (N + 1023) / 1024;
    int a = t * CH;
    int b = a + CH < N ? a + CH : N;
    int s = 0;
    for (int i = a; i < b; i++) s += deg[i];
    ssum[t] = s;
    __syncthreads();
    #pragma unroll
    for (int o = 1; o < 1024; o <<= 1) {
        int v = (t >= o) ? ssum[t - o] : 0;
        __syncthreads();
        ssum[t] += v;
        __syncthreads();
    }
    int base = (t == 0) ? 0 : ssum[t - 1];
    for (int i = a; i < b; i++) {
        off[i] = base; cur[i] = base; base += deg[i];
    }
    if (t == 1023) off[N] = E;
}

__global__ void scatter_kernel(const int* __restrict__ src, const int* __restrict__ dst,
                               int* __restrict__ cur, int* __restrict__ ss, int E) {
    int e = blockIdx.x * blockDim.x + threadIdx.x;
    if (e >= E) return;
    int p = atomicAdd(&cur[dst[e]], 1);
    ss[p] = src[e];
}

// ---------------- TF32 GEMM with cp.async double buffering (R5, measured) ----
#define GBM 128
#define GBN 64
#define GBK 32
#define AROW 36    // 36 % 32 == 4 -> fragment bank 4*gid+tig unique
#define BROW 72    // 72 % 32 == 8 -> fragment bank 8*tig+gid unique

__device__ __forceinline__ void cpa16(uint32_t dst, const void* src) {
    asm volatile("cp.async.cg.shared.global [%0], [%1], 16;" :: "r"(dst), "l"(src));
}

__global__ __launch_bounds__(256) void gemm_tf32(
    const float* __restrict__ A, const float* __restrict__ W,
    const float* __restrict__ bias, float* __restrict__ C,
    int M, int K, int Nc)
{
    extern __shared__ uint32_t sh[];
    uint32_t* As = sh;                          // [2][GBM][AROW]
    uint32_t* Bs = sh + 2 * GBM * AROW;         // [2][GBK][BROW]

    const int tid  = threadIdx.x;
    const int wid  = tid >> 5;
    const int lane = tid & 31;
    const int warpM = wid >> 1;
    const int warpN = wid & 1;
    const int gid = lane >> 2;
    const int tig = lane & 3;
    const int row0 = blockIdx.y * GBM;
    const int col0 = blockIdx.x * GBN;

    const int nch = K / GBK;
    float c[2][4][4] = {};

    #define STAGE(ch, buf) do {                                                   \
        int k0_ = (ch) * GBK;                                                     \
        _Pragma("unroll")                                                         \
        for (int i = 0; i < 4; i++) {                                             \
            int cc = tid + 256 * i;                    /* 0..1023 */              \
            int r  = cc >> 3;                          /* 0..127 */               \
            int kc = (cc & 7) << 2;                    /* 0,4..28 */              \
            uint32_t* dp = As + ((buf) * GBM + r) * AROW + kc;                    \
            if (row0 + r < M)                                                     \
                cpa16((uint32_t)__cvta_generic_to_shared(dp),                     \
                      A + (size_t)(row0 + r) * K + k0_ + kc);                     \
            else                                                                  \
                *(uint4*)dp = make_uint4(0u, 0u, 0u, 0u);                         \
        }                                                                         \
        _Pragma("unroll")                                                         \
        for (int i = 0; i < 2; i++) {                                             \
            int cc = tid + 256 * i;                    /* 0..511 */               \
            int r  = cc >> 4;                          /* 0..31 */                \
            int nc = (cc & 15) << 2;                   /* 0..60 */                \
            uint32_t* dp = Bs + ((buf) * GBK + r) * BROW + nc;                    \
            cpa16((uint32_t)__cvta_generic_to_shared(dp),                         \
                  W + (size_t)(k0_ + r) * Nc + col0 + nc);                        \
        }                                                                         \
        asm volatile("cp.async.commit_group;");                                   \
    } while (0)

    STAGE(0, 0);

    for (int ch = 0; ch < nch; ch++) {
        int buf = ch & 1;
        if (ch + 1 < nch) {
            STAGE(ch + 1, buf ^ 1);
            asm volatile("cp.async.wait_group 1;");
        } else {
            asm volatile("cp.async.wait_group 0;");
        }
        __syncthreads();

        const uint32_t* Ab = As + buf * GBM * AROW;
        const uint32_t* Bb = Bs + buf * GBK * BROW;

        #pragma unroll
        for (int ks = 0; ks < 4; ks++) {
            const int kk = ks * 8;
            uint32_t a[2][4], b[4][2];
            #pragma unroll
            for (int mi = 0; mi < 2; mi++) {
                int rb = warpM * 32 + mi * 16;
                a[mi][0] = rna(Ab[(rb + gid) * AROW + kk + tig]);
                a[mi][1] = rna(Ab[(rb + gid + 8) * AROW + kk + tig]);
                a[mi][2] = rna(Ab[(rb + gid) * AROW + kk + tig + 4]);
                a[mi][3] = rna(Ab[(rb + gid + 8) * AROW + kk + tig + 4]);
            }
            #pragma unroll
            for (int ni = 0; ni < 4; ni++) {
                int cb = warpN * 32 + ni * 8;
                b[ni][0] = rna(Bb[(kk + tig) * BROW + cb + gid]);
                b[ni][1] = rna(Bb[(kk + tig + 4) * BROW + cb + gid]);
            }
            #pragma unroll
            for (int mi = 0; mi < 2; mi++)
                #pragma unroll
                for (int ni = 0; ni < 4; ni++)
                    asm volatile(
                        "mma.sync.aligned.m16n8k8.row.col.f32.tf32.tf32.f32 "
                        "{%0,%1,%2,%3}, {%4,%5,%6,%7}, {%8,%9}, {%0,%1,%2,%3};"
                        : "+f"(c[mi][ni][0]), "+f"(c[mi][ni][1]),
                          "+f"(c[mi][ni][2]), "+f"(c[mi][ni][3])
                        : "r"(a[mi][0]), "r"(a[mi][1]), "r"(a[mi][2]), "r"(a[mi][3]),
                          "r"(b[ni][0]), "r"(b[ni][1]));
        }
        __syncthreads();
    }
    #undef STAGE

    #pragma unroll
    for (int mi = 0; mi < 2; mi++) {
        #pragma unroll
        for (int ni = 0; ni < 4; ni++) {
            int gcol = col0 + warpN * 32 + ni * 8 + tig * 2;
            float bx = bias[gcol], by = bias[gcol + 1];
            int r0 = row0 + warpM * 32 + mi * 16 + gid;
            if (r0 < M) {
                float2 o = make_float2(c[mi][ni][0] + bx, c[mi][ni][1] + by);
                *(float2*)(C + (size_t)r0 * Nc + gcol) = o;
            }
            int r1 = r0 + 8;
            if (r1 < M) {
                float2 o = make_float2(c[mi][ni][2] + bx, c[mi][ni][3] + by);
                *(float2*)(C + (size_t)r1 * Nc + gcol) = o;
            }
        }
    }
}

// ---------------- fused single-pass GATv2: online softmax, warp per node ------
// Each lane owns float2 (2*lane .. 2*lane+1) of each 64-dim head.
// Per edge: ONE fs gather feeds both logit computation and aggregation.
__global__ __launch_bounds__(256) void gat_online_kernel(
    const float* __restrict__ fs, const float* __restrict__ fd,
    const int* __restrict__ off, const int* __restrict__ ss,
    const float* __restrict__ attn, float* __restrict__ hout, int N)
{
    __shared__ float sattn[FT];
    if (threadIdx.x < FT) sattn[threadIdx.x] = attn[threadIdx.x];
    __syncthreads();

    int node = blockIdx.x * 8 + (threadIdx.x >> 5);
    int lane = threadIdx.x & 31;
    if (node >= N) return;
    int e0 = off[node], e1 = off[node + 1];

    float2 fdv[3], av[3];
    #pragma unroll
    for (int h = 0; h < 3; h++) {
        fdv[h] = *(const float2*)(fd + (size_t)node * FT + h * 64 + 2 * lane);
        av[h]  = *(const float2*)(sattn + h * 64 + 2 * lane);
    }

    float m0 = -3.0e38f, m1 = -3.0e38f, m2 = -3.0e38f;
    float den0 = 0.f, den1 = 0.f, den2 = 0.f;
    float ax0 = 0.f, ay0 = 0.f, ax1 = 0.f, ay1 = 0.f, ax2 = 0.f, ay2 = 0.f;

    for (int p = e0; p < e1; p++) {
        const float* fp = fs + (size_t)ss[p] * FT;
        float2 p0 = *(const float2*)(fp + 2 * lane);
        float2 p1 = *(const float2*)(fp + 64 + 2 * lane);
        float2 p2 = *(const float2*)(fp + 128 + 2 * lane);

        float t0 = lrelu(p0.x + fdv[0].x, 0.2f) * av[0].x
                 + lrelu(p0.y + fdv[0].y, 0.2f) * av[0].y;
        float t1 = lrelu(p1.x + fdv[1].x, 0.2f) * av[1].x
                 + lrelu(p1.y + fdv[1].y, 0.2f) * av[1].y;
        float t2 = lrelu(p2.x + fdv[2].x, 0.2f) * av[2].x
                 + lrelu(p2.y + fdv[2].y, 0.2f) * av[2].y;
        #pragma unroll
        for (int o = 16; o; o >>= 1) {
            t0 += __shfl_xor_sync(0xffffffffu, t0, o);
            t1 += __shfl_xor_sync(0xffffffffu, t1, o);
            t2 += __shfl_xor_sync(0xffffffffu, t2, o);
        }
        // online softmax update (all lanes hold identical t/m/den)
        float nm0 = fmaxf(m0, t0), nm1 = fmaxf(m1, t1), nm2 = fmaxf(m2, t2);
        float s0 = __expf(m0 - nm0), s1 = __expf(m1 - nm1), s2 = __expf(m2 - nm2);
        float w0 = __expf(t0 - nm0), w1 = __expf(t1 - nm1), w2 = __expf(t2 - nm2);
        m0 = nm0; m1 = nm1; m2 = nm2;
        den0 = den0 * s0 + w0; den1 = den1 * s1 + w1; den2 = den2 * s2 + w2;
        ax0 = fmaf(ax0, s0, w0 * p0.x);  ay0 = fmaf(ay0, s0, w0 * p0.y);
        ax1 = fmaf(ax1, s1, w1 * p1.x);  ay1 = fmaf(ay1, s1, w1 * p1.y);
        ax2 = fmaf(ax2, s2, w2 * p2.x);  ay2 = fmaf(ay2, s2, w2 * p2.y);
    }

    float r0 = 1.f / fmaxf(den0, 1e-9f);
    float r1 = 1.f / fmaxf(den1, 1e-9f);
    float r2 = 1.f / fmaxf(den2, 1e-9f);
    float* po = hout + (size_t)node * FT;
    *(float2*)(po + 2 * lane)       = make_float2(ax0 * r0, ay0 * r0);
    *(float2*)(po + 64 + 2 * lane)  = make_float2(ax1 * r1, ay1 * r1);
    *(float2*)(po + 128 + 2 * lane) = make_float2(ax2 * r2, ay2 * r2);
}

// ---------------- head-mean + per-graph pooling ----------------
__global__ void pool_kernel(const float* __restrict__ h, const int* __restrict__ gid,
                            float* __restrict__ pool, float* __restrict__ cnt, int N) {
    int idx = blockIdx.x * blockDim.x + threadIdx.x;
    if (idx >= N * OO) return;
    int n = idx >> 6, k = idx & 63;
    const float* p = h + (size_t)n * FT;
    float v = (p[k] + p[64 + k] + p[128 + k]) * (1.0f / 3.0f);
    int g = gid[n];
    atomicAdd(&pool[g * OO + k], v);
    if (k == 0) atomicAdd(&cnt[g], 1.0f);
}

// ---------------- final MLP: 64 -> 64 -> 32 -> 2, leaky 0.01 ----------------
__global__ void mlp_kernel(const float* __restrict__ pool, const float* __restrict__ cnt,
                           const float* __restrict__ W1, const float* __restrict__ b1,
                           const float* __restrict__ W2, const float* __restrict__ b2,
                           const float* __restrict__ W3, const float* __restrict__ b3,
                           float* __restrict__ out) {
    int g = blockIdx.x;
    int j = threadIdx.x;  // 64 threads
    __shared__ float gv[64], t1[64], t2[32];
    float c = fmaxf(cnt[g], 1.0f);
    gv[j] = pool[g * OO + j] / c;
    __syncthreads();
    float a = b1[j];
    #pragma unroll 8
    for (int k = 0; k < 64; k++) a = fmaf(gv[k], W1[k * 64 + j], a);
    t1[j] = lrelu(a, 0.01f);
    __syncthreads();
    if (j < 32) {
        float a2 = b2[j];
        #pragma unroll 8
        for (int k = 0; k < 64; k++) a2 = fmaf(t1[k], W2[k * 32 + j], a2);
        t2[j] = lrelu(a2, 0.01f);
    }
    __syncthreads();
    if (j < 2) {
        float a3 = b3[j];
        #pragma unroll
        for (int k = 0; k < 32; k++) a3 = fmaf(t2[k], W3[k * 2 + j], a3);
        out[g * 2 + j] = lrelu(a3, 0.01f);
    }
}

// ---------------- launcher ----------------
extern "C" void kernel_launch(void* const* d_in, const int* in_sizes, int n_in,
                              void* d_out, int out_size) {
    const float* x   = (const float*)d_in[0];
    const int*   src = (const int*)d_in[1];
    const int*   dst = (const int*)d_in[2];
    const int*   gid = (const int*)d_in[3];
    const float* Wsrc[3] = {(const float*)d_in[5],  (const float*)d_in[10], (const float*)d_in[15]};
    const float* bsrc[3] = {(const float*)d_in[6],  (const float*)d_in[11], (const float*)d_in[16]};
    const float* Wdst[3] = {(const float*)d_in[7],  (const float*)d_in[12], (const float*)d_in[17]};
    const float* bdst[3] = {(const float*)d_in[8],  (const float*)d_in[13], (const float*)d_in[18]};
    const float* attn[3] = {(const float*)d_in[9],  (const float*)d_in[14], (const float*)d_in[19]};
    const float* W1 = (const float*)d_in[20];
    const float* b1 = (const float*)d_in[21];
    const float* W2 = (const float*)d_in[22];
    const float* b2 = (const float*)d_in[23];
    const float* W3 = (const float*)d_in[24];
    const float* b3 = (const float*)d_in[25];

    const int N  = in_sizes[0] / 128;
    const int E  = in_sizes[1];
    const int ng = out_size / 2;

    float *fs, *fd, *ha, *hb, *pool, *cnt;
    int *deg, *off, *cur, *ssorted;
    cudaGetSymbolAddress((void**)&fs,   g_fs);
    cudaGetSymbolAddress((void**)&fd,   g_fd);
    cudaGetSymbolAddress((void**)&ha,   g_ha);
    cudaGetSymbolAddress((void**)&hb,   g_hb);
    cudaGetSymbolAddress((void**)&deg,  g_deg);
    cudaGetSymbolAddress((void**)&off,  g_off);
    cudaGetSymbolAddress((void**)&cur,  g_cur);
    cudaGetSymbolAddress((void**)&ssorted, g_ss);
    cudaGetSymbolAddress((void**)&pool, g_pool);
    cudaGetSymbolAddress((void**)&cnt,  g_cnt);

    // GEMM dynamic smem (55296 B > 48 KB static limit)
    const int GEMM_SMEM = (2 * GBM * AROW + 2 * GBK * BROW) * 4;
    cudaFuncSetAttribute(gemm_tf32, cudaFuncAttributeMaxDynamicSharedMemorySize, GEMM_SMEM);

    // ---- CSR build (once; reused by all 3 layers)
    cudaMemsetAsync(deg, 0, (size_t)N * sizeof(int), 0);
    hist_kernel<<<(E + 255) / 256, 256>>>(dst, deg, E);
    scan_kernel<<<1, 1024>>>(deg, off, cur, N, E);
    scatter_kernel<<<(E + 255) / 256, 256>>>(src, dst, cur, ssorted, E);

    const float* hin = x;
    int Fin = 128;
    float* houts[3] = {ha, hb, ha};
    const int nodeBlocks = (N + 7) / 8;

    for (int l = 0; l < 3; l++) {
        dim3 gg(FT / GBN, (N + GBM - 1) / GBM);
        gemm_tf32<<<gg, 256, GEMM_SMEM>>>(hin, Wsrc[l], bsrc[l], fs, N, Fin, FT);
        gemm_tf32<<<gg, 256, GEMM_SMEM>>>(hin, Wdst[l], bdst[l], fd, N, Fin, FT);
        gat_online_kernel<<<nodeBlocks, 256>>>(fs, fd, off, ssorted, attn[l], houts[l], N);
        hin = houts[l];
        Fin = FT;
    }

    cudaMemsetAsync(pool, 0, 128 * OO * sizeof(float), 0);
    cudaMemsetAsync(cnt,  0, 128 * sizeof(float), 0);
    pool_kernel<<<(N * OO + 255) / 256, 256>>>(hin, gid, pool, cnt, N);
    mlp_kernel<<<ng, 64>>>(pool, cnt, W1, b1, W2, b2, W3, b3, (float*)d_out);
}